// round 7
// baseline (speedup 1.0000x reference)
#include <cuda_runtime.h>

// Problem constants (fixed by the dataset instance)
#define D_DIM   1024
#define E_DIM   64
#define TOPK    8
#define B_DIM   4
#define ALPHA   0.1f
#define EPS_R   1e-20f

#define THREADS 256
#define TPB     64       // tokens per tile
#define KC      64       // k-chunk
#define NCHUNK  (D_DIM / KC)          // 16
#define ROW_STR 68       // padded smem row stride (floats); 68*4=272B
#define TILE_FL (TPB * ROW_STR + E_DIM * ROW_STR)   // 8704 floats per buffer
#define JT      4        // tokens per thread
#define RT      4        // experts per thread

// scratch (no allocation allowed -> device globals, zero-initialized)
__device__ float g_ce[B_DIM * E_DIM];
__device__ float g_ssum[B_DIM * E_DIM];
__device__ unsigned int g_count;
__device__ unsigned int g_tile;

// packed f32x2 FMA: d.lo += a.lo*b.lo; d.hi += a.hi*b.hi  (one issue slot)
__device__ __forceinline__ void fma2(unsigned long long& d,
                                     unsigned long long a,
                                     unsigned long long b) {
    asm("fma.rn.f32x2 %0, %1, %2, %0;" : "+l"(d) : "l"(a), "l"(b));
}

__device__ __forceinline__ float fold2(unsigned long long v) {
    float lo, hi;
    asm("mov.b64 {%0, %1}, %2;" : "=f"(lo), "=f"(hi) : "l"(v));
    return lo + hi;
}

__device__ __forceinline__ void cp16(unsigned dst, const void* src) {
    asm volatile("cp.async.ca.shared.global [%0], [%1], 16;\n"
                 :: "r"(dst), "l"(src));
}
__device__ __forceinline__ void cp_commit() {
    asm volatile("cp.async.commit_group;\n");
}
template <int N>
__device__ __forceinline__ void cp_wait() {
    asm volatile("cp.async.wait_group %0;\n" :: "n"(N));
}

__global__ __launch_bounds__(THREADS, 2)
void moe_gate_kernel(const float* __restrict__ x,
                     const float* __restrict__ W,
                     float* __restrict__ out_idx,
                     float* __restrict__ out_w,
                     float* __restrict__ out_aux,
                     int S, int nblocks, int ntiles)
{
    extern __shared__ float smem_dyn[];   // 2 * TILE_FL floats (double buffer)
    __shared__ float sm_cnt[E_DIM];
    __shared__ float sm_ssum[E_DIM];
    __shared__ unsigned int sm_ticket;
    __shared__ unsigned int sm_tile;

    const unsigned sbase = (unsigned)__cvta_generic_to_shared(smem_dyn);
    const int tid = threadIdx.x;
    const int et  = tid & 15;     // expert lane 0..15 (owns experts et + 16r)
    const int tt  = tid >> 4;     // token thread 0..15 (owns tokens tt + 16j)
    const unsigned fullmask = 0xffffffffu;

    // ---------------- dynamic tile loop (ticket-scheduled) ----------------
    for (;;) {
        if (tid == 0) sm_tile = atomicAdd(&g_tile, 1u);
        __syncthreads();
        const unsigned tile = sm_tile;
        __syncthreads();
        if (tile >= (unsigned)ntiles) break;
        const long t0 = (long)tile * TPB;

        float acc[JT][RT];   // Kahan running sums
        float cmp[JT][RT];   // Kahan compensation
#pragma unroll
        for (int j = 0; j < JT; j++)
#pragma unroll
            for (int r = 0; r < RT; r++) { acc[j][r] = 0.0f; cmp[j][r] = 0.0f; }

        // -------- prefetch chunk 0 --------
        {
            const unsigned xb = sbase;                       // buffer 0
            const unsigned wb = sbase + TPB * ROW_STR * 4;
            // x tile: 64 tokens x 16 float4 = 1024 f4 -> 4 per thread
#pragma unroll
            for (int p = 0; p < 4; p++) {
                int idx = tid + THREADS * p;
                int tok = idx >> 4, kq = idx & 15;
                cp16(xb + (tok * ROW_STR + kq * 4) * 4,
                     &x[(t0 + tok) * D_DIM + kq * 4]);
            }
            // W tile: 64 experts x 16 float4 = 1024 f4 -> 4 per thread
#pragma unroll
            for (int p = 0; p < 4; p++) {
                int idx = tid + THREADS * p;
                int e = idx >> 4, kq = idx & 15;
                cp16(wb + (e * ROW_STR + kq * 4) * 4,
                     &W[e * D_DIM + kq * 4]);
            }
            cp_commit();
        }

        // ---------------- GEMM main loop ----------------
#pragma unroll 1
        for (int c = 0; c < NCHUNK; c++) {
            if (c + 1 < NCHUNK) {
                const int k0 = (c + 1) * KC;
                const unsigned buf = ((unsigned)(c + 1) & 1u) * TILE_FL * 4;
                const unsigned xb = sbase + buf;
                const unsigned wb = xb + TPB * ROW_STR * 4;
#pragma unroll
                for (int p = 0; p < 4; p++) {
                    int idx = tid + THREADS * p;
                    int tok = idx >> 4, kq = idx & 15;
                    cp16(xb + (tok * ROW_STR + kq * 4) * 4,
                         &x[(t0 + tok) * D_DIM + k0 + kq * 4]);
                }
#pragma unroll
                for (int p = 0; p < 4; p++) {
                    int idx = tid + THREADS * p;
                    int e = idx >> 4, kq = idx & 15;
                    cp16(wb + (e * ROW_STR + kq * 4) * 4,
                         &W[e * D_DIM + k0 + kq * 4]);
                }
                cp_commit();
                cp_wait<1>();   // chunk c arrived; chunk c+1 in flight
            } else {
                cp_wait<0>();
            }
            __syncthreads();

            const float* xb = smem_dyn + (c & 1) * TILE_FL;
            const float* wb = xb + TPB * ROW_STR;

            unsigned long long cacc2[JT][RT];
#pragma unroll
            for (int j = 0; j < JT; j++)
#pragma unroll
                for (int r = 0; r < RT; r++) cacc2[j][r] = 0ULL;

#pragma unroll
            for (int kq = 0; kq < 16; kq++) {
                ulonglong2 xv[JT], wv[RT];
#pragma unroll
                for (int j = 0; j < JT; j++)
                    xv[j] = *(const ulonglong2*)&xb[(tt + 16 * j) * ROW_STR + kq * 4];
#pragma unroll
                for (int r = 0; r < RT; r++)
                    wv[r] = *(const ulonglong2*)&wb[(et + 16 * r) * ROW_STR + kq * 4];
#pragma unroll
                for (int j = 0; j < JT; j++)
#pragma unroll
                    for (int r = 0; r < RT; r++) {
                        fma2(cacc2[j][r], xv[j].x, wv[r].x);
                        fma2(cacc2[j][r], xv[j].y, wv[r].y);
                    }
            }

            // fold packed partials, Kahan-add into running accumulators
#pragma unroll
            for (int j = 0; j < JT; j++)
#pragma unroll
                for (int r = 0; r < RT; r++) {
                    float cs = fold2(cacc2[j][r]);
                    float y = cs - cmp[j][r];
                    float t = acc[j][r] + y;
                    cmp[j][r] = (t - acc[j][r]) - y;
                    acc[j][r] = t;
                }
            __syncthreads();   // buffer (c&1) is cp.async target in iter c+1
        }

        // ---------------- epilogue: softmax + top-8 + stats ----------------
        if (tid < E_DIM) { sm_cnt[tid] = 0.0f; sm_ssum[tid] = 0.0f; }
        __syncthreads();

        float loc_ssum[RT];
#pragma unroll
        for (int r = 0; r < RT; r++) loc_ssum[r] = 0.0f;

#pragma unroll 1
        for (int j = 0; j < JT; j++) {
            // softmax over 64 experts: 16 lanes (et) x 4 regs
            float m = acc[j][0];
#pragma unroll
            for (int r = 1; r < RT; r++) m = fmaxf(m, acc[j][r]);
#pragma unroll
            for (int d = 1; d < 16; d <<= 1)
                m = fmaxf(m, __shfl_xor_sync(fullmask, m, d));

            float sc[RT];
            float s = 0.0f;
#pragma unroll
            for (int r = 0; r < RT; r++) { sc[r] = expf(acc[j][r] - m); s += sc[r]; }
#pragma unroll
            for (int d = 1; d < 16; d <<= 1)
                s += __shfl_xor_sync(fullmask, s, d);
            // exact IEEE division to mirror XLA softmax
#pragma unroll
            for (int r = 0; r < RT; r++) { sc[r] = sc[r] / s; loc_ssum[r] += sc[r]; }

            // iterative top-8 (destructive on sc); tie-break: lower index
            float tv[TOPK]; int ti[TOPK];
#pragma unroll 1
            for (int it = 0; it < TOPK; it++) {
                float bv = -1.0f; int bi = E_DIM;
#pragma unroll
                for (int r = 0; r < RT; r++) {
                    if (sc[r] > bv) { bv = sc[r]; bi = et + 16 * r; }
                }
#pragma unroll
                for (int d = 1; d < 16; d <<= 1) {
                    float ov = __shfl_xor_sync(fullmask, bv, d);
                    int   oi = __shfl_xor_sync(fullmask, bi, d);
                    if (ov > bv || (ov == bv && oi < bi)) { bv = ov; bi = oi; }
                }
                if ((bi & 15) == et) sc[bi >> 4] = -1.0f;  // owner clears winner
                tv[it] = bv; ti[it] = bi;
            }

            if (et == 0) {
                float wsum = 0.0f;
#pragma unroll
                for (int it = 0; it < TOPK; it++) wsum += tv[it];
                wsum += EPS_R;
                long t = t0 + tt + 16 * j;
#pragma unroll
                for (int it = 0; it < TOPK; it++) {
                    out_idx[t * TOPK + it] = (float)ti[it];
                    out_w  [t * TOPK + it] = tv[it] / wsum;
                    atomicAdd(&sm_cnt[ti[it]], 1.0f);
                }
            }
        }

#pragma unroll
        for (int r = 0; r < RT; r++)
            atomicAdd(&sm_ssum[et + 16 * r], loc_ssum[r]);
        __syncthreads();

        if (tid < E_DIM) {
            int b = (int)(t0 / (long)S);       // tile is batch-aligned (64 | 8192)
            atomicAdd(&g_ce[b * E_DIM + tid],   sm_cnt[tid]);
            atomicAdd(&g_ssum[b * E_DIM + tid], sm_ssum[tid]);
        }
        __syncthreads();
    }

    // ---------------- fused aux finalization (last CTA) ----------------
    __threadfence();
    if (tid == 0) sm_ticket = atomicAdd(&g_count, 1u);
    __syncthreads();

    if (sm_ticket == (unsigned)(nblocks - 1)) {
        __threadfence();
        const volatile float* ce = g_ce;
        const volatile float* ss = g_ssum;
        float v = ce[tid] * ss[tid];          // 256 threads cover B*E = 256
        float* red = smem_dyn;
        red[tid] = v;
        __syncthreads();
        for (int off = 128; off > 0; off >>= 1) {
            if (tid < off) red[tid] += red[tid + off];
            __syncthreads();
        }
        if (tid == 0)
            out_aux[0] = red[0] / (float)S / (float)B_DIM * ALPHA;
        // reset scratch for the next graph replay
        g_ce[tid] = 0.0f; g_ssum[tid] = 0.0f;
        if (tid == 0) { g_count = 0u; g_tile = 0u; }
    }
}

extern "C" void kernel_launch(void* const* d_in, const int* in_sizes, int n_in,
                              void* d_out, int out_size) {
    const float* x = (const float*)d_in[0];
    const float* W = (const float*)d_in[1];
    const int T = in_sizes[0] / D_DIM;       // 32768
    const int S = T / B_DIM;                 // 8192
    const int ntiles = T / TPB;              // 512
    const int nblocks = 2 * 148;             // fill all resident slots

    float* out     = (float*)d_out;
    float* out_idx = out;                         // [T,8] indices as float
    float* out_w   = out + (size_t)T * TOPK;      // [T,8] weights
    float* out_aux = out + (out_size - 1);        // scalar aux loss

    const int smem_bytes = 2 * TILE_FL * (int)sizeof(float);  // ~69.6 KB
    cudaFuncSetAttribute(moe_gate_kernel,
                         cudaFuncAttributeMaxDynamicSharedMemorySize, smem_bytes);
    moe_gate_kernel<<<nblocks, THREADS, smem_bytes>>>(x, W, out_idx, out_w,
                                                      out_aux, S, nblocks, ntiles);
}

// round 9
// speedup vs baseline: 1.0349x; 1.0349x over previous
#include <cuda_runtime.h>
#include <cstdint>

// Problem constants
#define D_DIM   1024
#define E_DIM   64
#define TOPK    8
#define B_DIM   4
#define ALPHA   0.1f
#define EPS_R   1e-20f

#define THREADS 256
#define TPB     128              // tokens per CTA
#define KC      64               // K per chunk
#define NCHUNK  (D_DIM / KC)     // 16

// smem tile layout: bf16, 64 cols used, row stride 72 bf16 = 144 B (odd*16B -> conflict-free)
#define STR_B   144
#define XT_BYTES (TPB * STR_B)        // 18432
#define WT_BYTES (E_DIM * STR_B)      // 9216
#define OFF_X1 0
#define OFF_X2 (OFF_X1 + XT_BYTES)
#define OFF_X3 (OFF_X2 + XT_BYTES)
#define OFF_W1 (OFF_X3 + XT_BYTES)
#define OFF_W2 (OFF_W1 + WT_BYTES)
#define OFF_W3 (OFF_W2 + WT_BYTES)
#define SMEM_BYTES (OFF_W3 + WT_BYTES)   // 82944
#define LOG_STR 66                        // padded logits row (floats)

// device-global scratch (no allocation allowed)
__device__ float g_ce[B_DIM * E_DIM];
__device__ float g_ssum[B_DIM * E_DIM];
__device__ unsigned int g_count;

// ------------------------- helpers -------------------------
// exact 3-way bf16 split of fp32 (subtractions exact)
__device__ __forceinline__ void split3(float v, uint32_t& a, uint32_t& b, uint32_t& c) {
    uint16_t h;
    asm("cvt.rn.bf16.f32 %0, %1;" : "=h"(h) : "f"(v));
    a = h;
    float r = v - __uint_as_float((uint32_t)h << 16);
    asm("cvt.rn.bf16.f32 %0, %1;" : "=h"(h) : "f"(r));
    b = h;
    float r2 = r - __uint_as_float((uint32_t)h << 16);
    asm("cvt.rn.bf16.f32 %0, %1;" : "=h"(h) : "f"(r2));
    c = h;
}

__device__ __forceinline__ void store_split_f4(char* sm, uint32_t byte_off, float4 v,
                                               int o1, int o2, int o3) {
    uint32_t a0,b0,c0,a1,b1,c1,a2,b2,c2,a3,b3,c3;
    split3(v.x,a0,b0,c0); split3(v.y,a1,b1,c1);
    split3(v.z,a2,b2,c2); split3(v.w,a3,b3,c3);
    *(uint2*)(sm + o1 + byte_off) = make_uint2(a0 | (a1 << 16), a2 | (a3 << 16));
    *(uint2*)(sm + o2 + byte_off) = make_uint2(b0 | (b1 << 16), b2 | (b3 << 16));
    *(uint2*)(sm + o3 + byte_off) = make_uint2(c0 | (c1 << 16), c2 | (c3 << 16));
}

__device__ __forceinline__ void ldm_x4(uint32_t& r0, uint32_t& r1, uint32_t& r2,
                                       uint32_t& r3, uint32_t addr) {
    asm volatile("ldmatrix.sync.aligned.m8n8.x4.shared.b16 {%0,%1,%2,%3}, [%4];"
                 : "=r"(r0),"=r"(r1),"=r"(r2),"=r"(r3) : "r"(addr));
}
__device__ __forceinline__ void ldm_x2(uint32_t& r0, uint32_t& r1, uint32_t addr) {
    asm volatile("ldmatrix.sync.aligned.m8n8.x2.shared.b16 {%0,%1}, [%2];"
                 : "=r"(r0),"=r"(r1) : "r"(addr));
}

__device__ __forceinline__ void mma_bf16(float* c, const uint32_t* a,
                                         uint32_t b0, uint32_t b1) {
    asm volatile(
        "mma.sync.aligned.m16n8k16.row.col.f32.bf16.bf16.f32 "
        "{%0,%1,%2,%3}, {%4,%5,%6,%7}, {%8,%9}, {%0,%1,%2,%3};"
        : "+f"(c[0]), "+f"(c[1]), "+f"(c[2]), "+f"(c[3])
        : "r"(a[0]), "r"(a[1]), "r"(a[2]), "r"(a[3]), "r"(b0), "r"(b1));
}

// ------------------------- kernel -------------------------
__global__ __launch_bounds__(THREADS, 2)
void moe_gate_kernel(const float* __restrict__ x,
                     const float* __restrict__ W,
                     float* __restrict__ out_idx,
                     float* __restrict__ out_w,
                     float* __restrict__ out_aux,
                     int S, int nblocks)
{
    extern __shared__ char smem[];
    __shared__ float sm_cnt[E_DIM];
    __shared__ float sm_ssum[E_DIM];
    __shared__ unsigned int sm_ticket;

    const int tid  = threadIdx.x;
    const int wid  = tid >> 5;
    const int lane = tid & 31;
    const long t0  = (long)blockIdx.x * TPB;
    const unsigned fullmask = 0xffffffffu;

    const uint32_t smem_u = (uint32_t)__cvta_generic_to_shared(smem);
    const int m_base = wid * 16;   // warp's token rows

    if (tid < E_DIM) { sm_cnt[tid] = 0.0f; sm_ssum[tid] = 0.0f; }
    __syncthreads();

    // A-fragment ldmatrix address components (row = lane%16, k-half = lane/16)
    const uint32_t a_row_off = (uint32_t)(m_base + (lane & 15)) * STR_B
                             + (uint32_t)(lane >> 4) * 16;
    // B-fragment ldmatrix address components (row = lane%8, k-half = (lane/8)&1)
    const uint32_t b_row_off = (uint32_t)(lane & 7) * STR_B
                             + (uint32_t)((lane >> 3) & 1) * 16;

    float acc[8][4], cmp[8][4];
#pragma unroll
    for (int nt = 0; nt < 8; nt++)
#pragma unroll
        for (int q = 0; q < 4; q++) { acc[nt][q] = 0.0f; cmp[nt][q] = 0.0f; }

    // ---------------- GEMM: bf16x6 split mma + per-chunk Kahan ----------------
#pragma unroll 1
    for (int c = 0; c < NCHUNK; c++) {
        const int k0 = c * KC;

        // split + store x chunk: 128 tok x 16 float4 -> 8 per thread
#pragma unroll
        for (int p = 0; p < 8; p++) {
            int idx = tid + THREADS * p;
            int tok = idx >> 4, kq = idx & 15;
            float4 v = *(const float4*)&x[(t0 + tok) * D_DIM + k0 + kq * 4];
            store_split_f4(smem, (uint32_t)(tok * STR_B + kq * 8), v,
                           OFF_X1, OFF_X2, OFF_X3);
        }
        // split + store W chunk: 64 exp x 16 float4 -> 4 per thread
#pragma unroll
        for (int p = 0; p < 4; p++) {
            int idx = tid + THREADS * p;
            int e = idx >> 4, kq = idx & 15;
            float4 v = *(const float4*)&W[e * D_DIM + k0 + kq * 4];
            store_split_f4(smem, (uint32_t)(e * STR_B + kq * 8), v,
                           OFF_W1, OFF_W2, OFF_W3);
        }
        __syncthreads();

        // two n-half passes to bound register pressure
#pragma unroll 1
        for (int rh = 0; rh < 2; rh++) {
            float cacc[4][4];
#pragma unroll
            for (int nt = 0; nt < 4; nt++)
#pragma unroll
                for (int q = 0; q < 4; q++) cacc[nt][q] = 0.0f;

#pragma unroll
            for (int ks = 0; ks < 4; ks++) {
                const uint32_t a_off = a_row_off + (uint32_t)ks * 32;
                uint32_t a1[4], a2[4], a3[4];
                ldm_x4(a1[0],a1[1],a1[2],a1[3], smem_u + OFF_X1 + a_off);
                ldm_x4(a2[0],a2[1],a2[2],a2[3], smem_u + OFF_X2 + a_off);
                ldm_x4(a3[0],a3[1],a3[2],a3[3], smem_u + OFF_X3 + a_off);

#pragma unroll
                for (int nt = 0; nt < 4; nt++) {
                    const uint32_t b_off = b_row_off
                        + (uint32_t)((rh * 4 + nt) * 8) * STR_B
                        + (uint32_t)ks * 32;
                    uint32_t b1a, b1b, b2a, b2b, b3a, b3b;
                    ldm_x2(b1a, b1b, smem_u + OFF_W1 + b_off);
                    ldm_x2(b2a, b2b, smem_u + OFF_W2 + b_off);
                    ldm_x2(b3a, b3b, smem_u + OFF_W3 + b_off);

                    mma_bf16(cacc[nt], a1, b1a, b1b);   // x1*w1
                    mma_bf16(cacc[nt], a1, b2a, b2b);   // x1*w2
                    mma_bf16(cacc[nt], a2, b1a, b1b);   // x2*w1
                    mma_bf16(cacc[nt], a1, b3a, b3b);   // x1*w3
                    mma_bf16(cacc[nt], a2, b2a, b2b);   // x2*w2
                    mma_bf16(cacc[nt], a3, b1a, b1b);   // x3*w1
                }
            }

            // Kahan-fold chunk sums into running accumulators
#pragma unroll
            for (int nt = 0; nt < 4; nt++)
#pragma unroll
                for (int q = 0; q < 4; q++) {
                    int n = rh * 4 + nt;
                    float y = cacc[nt][q] - cmp[n][q];
                    float t = acc[n][q] + y;
                    cmp[n][q] = (t - acc[n][q]) - y;
                    acc[n][q] = t;
                }
        }
        __syncthreads();   // smem tiles rewritten next chunk
    }

    // ---------------- logits -> smem ----------------
    float* logit = (float*)smem;
    {
        const int r0 = m_base + (lane >> 2);
        const int c0 = (lane & 3) * 2;
#pragma unroll
        for (int nt = 0; nt < 8; nt++) {
            *(float2*)&logit[r0 * LOG_STR + nt * 8 + c0]
                = make_float2(acc[nt][0], acc[nt][1]);
            *(float2*)&logit[(r0 + 8) * LOG_STR + nt * 8 + c0]
                = make_float2(acc[nt][2], acc[nt][3]);
        }
    }
    __syncthreads();

    // ---------------- epilogue: softmax + top-8 + stats (proven path) --------
    const int et = tid & 15;      // expert lane 0..15 (experts et + 16r)
    const int tt = tid >> 4;      // token thread 0..15 (tokens tt + 16j)

    float loc_ssum[4] = {0.0f, 0.0f, 0.0f, 0.0f};

#pragma unroll 1
    for (int j = 0; j < 8; j++) {
        const int token = tt + 16 * j;
        float a[4];
#pragma unroll
        for (int r = 0; r < 4; r++)
            a[r] = logit[token * LOG_STR + et + 16 * r];

        float m = a[0];
#pragma unroll
        for (int r = 1; r < 4; r++) m = fmaxf(m, a[r]);
#pragma unroll
        for (int d = 1; d < 16; d <<= 1)
            m = fmaxf(m, __shfl_xor_sync(fullmask, m, d));

        float sc[4];
        float s = 0.0f;
#pragma unroll
        for (int r = 0; r < 4; r++) { sc[r] = expf(a[r] - m); s += sc[r]; }
#pragma unroll
        for (int d = 1; d < 16; d <<= 1)
            s += __shfl_xor_sync(fullmask, s, d);
#pragma unroll
        for (int r = 0; r < 4; r++) { sc[r] = sc[r] / s; loc_ssum[r] += sc[r]; }

        float tv[TOPK]; int ti[TOPK];
#pragma unroll 1
        for (int it = 0; it < TOPK; it++) {
            float bv = -1.0f; int bi = E_DIM;
#pragma unroll
            for (int r = 0; r < 4; r++)
                if (sc[r] > bv) { bv = sc[r]; bi = et + 16 * r; }
#pragma unroll
            for (int d = 1; d < 16; d <<= 1) {
                float ov = __shfl_xor_sync(fullmask, bv, d);
                int   oi = __shfl_xor_sync(fullmask, bi, d);
                if (ov > bv || (ov == bv && oi < bi)) { bv = ov; bi = oi; }
            }
            if ((bi & 15) == et) sc[bi >> 4] = -1.0f;
            tv[it] = bv; ti[it] = bi;
        }

        if (et == 0) {
            float wsum = 0.0f;
#pragma unroll
            for (int it = 0; it < TOPK; it++) wsum += tv[it];
            wsum += EPS_R;
            long t = t0 + token;
#pragma unroll
            for (int it = 0; it < TOPK; it++) {
                out_idx[t * TOPK + it] = (float)ti[it];
                out_w  [t * TOPK + it] = tv[it] / wsum;
                atomicAdd(&sm_cnt[ti[it]], 1.0f);
            }
        }
    }

#pragma unroll
    for (int r = 0; r < 4; r++)
        atomicAdd(&sm_ssum[et + 16 * r], loc_ssum[r]);
    __syncthreads();

    if (tid < E_DIM) {
        int b = (int)(t0 / (long)S);      // tile batch-aligned (128 | 8192)
        atomicAdd(&g_ce[b * E_DIM + tid],   sm_cnt[tid]);
        atomicAdd(&g_ssum[b * E_DIM + tid], sm_ssum[tid]);
    }

    // ---------------- fused aux finalization (last CTA) ----------------
    __threadfence();
    if (tid == 0) sm_ticket = atomicAdd(&g_count, 1u);
    __syncthreads();

    if (sm_ticket == (unsigned)(nblocks - 1)) {
        __threadfence();
        const volatile float* ce = g_ce;
        const volatile float* ss = g_ssum;
        float v = ce[tid] * ss[tid];          // 256 threads cover B*E = 256
        float* red = (float*)smem;
        red[tid] = v;
        __syncthreads();
        for (int off = 128; off > 0; off >>= 1) {
            if (tid < off) red[tid] += red[tid + off];
            __syncthreads();
        }
        if (tid == 0)
            out_aux[0] = red[0] / (float)S / (float)B_DIM * ALPHA;
        // reset scratch for the next graph replay
        g_ce[tid] = 0.0f; g_ssum[tid] = 0.0f;
        if (tid == 0) g_count = 0u;
    }
}

extern "C" void kernel_launch(void* const* d_in, const int* in_sizes, int n_in,
                              void* d_out, int out_size) {
    const float* x = (const float*)d_in[0];
    const float* W = (const float*)d_in[1];
    const int T = in_sizes[0] / D_DIM;     // 32768
    const int S = T / B_DIM;               // 8192
    const int nblocks = T / TPB;           // 256

    float* out     = (float*)d_out;
    float* out_idx = out;                         // [T,8] indices as float
    float* out_w   = out + (size_t)T * TOPK;      // [T,8] weights
    float* out_aux = out + (out_size - 1);        // scalar aux loss

    cudaFuncSetAttribute(moe_gate_kernel,
                         cudaFuncAttributeMaxDynamicSharedMemorySize, SMEM_BYTES);
    moe_gate_kernel<<<nblocks, THREADS, SMEM_BYTES>>>(x, W, out_idx, out_w,
                                                      out_aux, S, nblocks);
}

// round 10
// speedup vs baseline: 1.2179x; 1.1768x over previous
#include <cuda_runtime.h>
#include <cstdint>

// Problem constants
#define D_DIM   1024
#define E_DIM   64
#define TOPK    8
#define B_DIM   4
#define ALPHA   0.1f
#define EPS_R   1e-20f

#define THREADS 512
#define TPB     128              // tokens per CTA
#define KC      64               // K per chunk
#define NCHUNK  (D_DIM / KC)     // 16

// smem: bf16 tiles, 64 cols used, row stride 72 bf16 = 144 B (conflict-free ldmatrix)
#define STR_B   144
#define XT_B    (TPB * STR_B)         // 18432
#define WT_B    (E_DIM * STR_B)       // 9216
#define OFF_X1  0
#define OFF_X2  (OFF_X1 + XT_B)
#define OFF_X3  (OFF_X2 + XT_B)
#define OFF_W1  (OFF_X3 + XT_B)
#define OFF_W2  (OFF_W1 + WT_B)
#define OFF_W3  (OFF_W2 + WT_B)
#define BUF_B   (OFF_W3 + WT_B)       // 82944 per buffer
#define SMEM_BYTES (2 * BUF_B)        // 165888
#define LOG_STR 66                    // padded logits row (floats)

// device-global scratch (static — no allocation)
__device__ uint16_t g_ws[3 * E_DIM * D_DIM];   // pre-split W (bf16 bits)
__device__ float g_ce[B_DIM * E_DIM];
__device__ float g_ssum[B_DIM * E_DIM];
__device__ unsigned int g_count;

// ------------------------- helpers -------------------------
__device__ __forceinline__ void split3(float v, uint32_t& a, uint32_t& b, uint32_t& c) {
    uint16_t h;
    asm("cvt.rn.bf16.f32 %0, %1;" : "=h"(h) : "f"(v));
    a = h;
    float r = v - __uint_as_float((uint32_t)h << 16);
    asm("cvt.rn.bf16.f32 %0, %1;" : "=h"(h) : "f"(r));
    b = h;
    float r2 = r - __uint_as_float((uint32_t)h << 16);
    asm("cvt.rn.bf16.f32 %0, %1;" : "=h"(h) : "f"(r2));
    c = h;
}

__device__ __forceinline__ void store_split_f4(char* sm, uint32_t byte_off, float4 v) {
    uint32_t a0,b0,c0,a1,b1,c1,a2,b2,c2,a3,b3,c3;
    split3(v.x,a0,b0,c0); split3(v.y,a1,b1,c1);
    split3(v.z,a2,b2,c2); split3(v.w,a3,b3,c3);
    *(uint2*)(sm + OFF_X1 + byte_off) = make_uint2(a0 | (a1 << 16), a2 | (a3 << 16));
    *(uint2*)(sm + OFF_X2 + byte_off) = make_uint2(b0 | (b1 << 16), b2 | (b3 << 16));
    *(uint2*)(sm + OFF_X3 + byte_off) = make_uint2(c0 | (c1 << 16), c2 | (c3 << 16));
}

__device__ __forceinline__ void ldm_x4(uint32_t& r0, uint32_t& r1, uint32_t& r2,
                                       uint32_t& r3, uint32_t addr) {
    asm volatile("ldmatrix.sync.aligned.m8n8.x4.shared.b16 {%0,%1,%2,%3}, [%4];"
                 : "=r"(r0),"=r"(r1),"=r"(r2),"=r"(r3) : "r"(addr));
}
__device__ __forceinline__ void ldm_x2(uint32_t& r0, uint32_t& r1, uint32_t addr) {
    asm volatile("ldmatrix.sync.aligned.m8n8.x2.shared.b16 {%0,%1}, [%2];"
                 : "=r"(r0),"=r"(r1) : "r"(addr));
}

__device__ __forceinline__ void mma_bf16(float* c, const uint32_t* a,
                                         uint32_t b0, uint32_t b1) {
    asm volatile(
        "mma.sync.aligned.m16n8k16.row.col.f32.bf16.bf16.f32 "
        "{%0,%1,%2,%3}, {%4,%5,%6,%7}, {%8,%9}, {%0,%1,%2,%3};"
        : "+f"(c[0]), "+f"(c[1]), "+f"(c[2]), "+f"(c[3])
        : "r"(a[0]), "r"(a[1]), "r"(a[2]), "r"(a[3]), "r"(b0), "r"(b1));
}

__device__ __forceinline__ void cp16(unsigned dst, const void* src) {
    asm volatile("cp.async.ca.shared.global [%0], [%1], 16;\n" :: "r"(dst), "l"(src));
}
__device__ __forceinline__ void cp_commit() {
    asm volatile("cp.async.commit_group;\n");
}
template <int N>
__device__ __forceinline__ void cp_wait() {
    asm volatile("cp.async.wait_group %0;\n" :: "n"(N));
}

// ------------------------- W pre-split kernel -------------------------
__global__ void wsplit_kernel(const float* __restrict__ W) {
    int i = blockIdx.x * blockDim.x + threadIdx.x;
    if (i < E_DIM * D_DIM) {
        uint32_t a, b, c;
        split3(W[i], a, b, c);
        g_ws[i]                    = (uint16_t)a;
        g_ws[E_DIM * D_DIM + i]    = (uint16_t)b;
        g_ws[2 * E_DIM * D_DIM + i] = (uint16_t)c;
    }
}

// ------------------------- main kernel -------------------------
__global__ __launch_bounds__(THREADS, 1)
void moe_gate_kernel(const float* __restrict__ x,
                     float* __restrict__ out_idx,
                     float* __restrict__ out_w,
                     float* __restrict__ out_aux,
                     int S, int nblocks)
{
    extern __shared__ char smem[];
    __shared__ float sm_cnt[E_DIM];
    __shared__ float sm_ssum[E_DIM];
    __shared__ unsigned int sm_ticket;

    const int tid  = threadIdx.x;
    const int wid  = tid >> 5;
    const int lane = tid & 31;
    const long t0  = (long)blockIdx.x * TPB;
    const unsigned fullmask = 0xffffffffu;

    const uint32_t smem_u = (uint32_t)__cvta_generic_to_shared(smem);

    // warp tile: 16 tokens x 32 experts
    const int tok_grp = wid >> 1;            // 0..7
    const int eh      = wid & 1;             // expert half (0/1)
    const int m_base  = tok_grp * 16;

    if (tid < E_DIM) { sm_cnt[tid] = 0.0f; sm_ssum[tid] = 0.0f; }

    // ldmatrix per-lane address components (validated in round 9)
    const uint32_t a_row_off = (uint32_t)(m_base + (lane & 15)) * STR_B
                             + (uint32_t)(lane >> 4) * 16;
    const uint32_t b_row_off = (uint32_t)(lane & 7) * STR_B
                             + (uint32_t)((lane >> 3) & 1) * 16
                             + (uint32_t)(eh * 32) * STR_B;

    // per-thread load indices: x tile 2048 f4 / 512 thr = 4; W cp 1536 / 512 = 3
    const int x_kq  = tid & 15;          // float4 col
    const int x_tok = tid >> 4;          // +32p
    const int w_e   = tid >> 3;          // expert row (0..63)
    const int w_seg = tid & 7;           // 16B segment

    float acc[4][4], cmp[4][4];
#pragma unroll
    for (int nt = 0; nt < 4; nt++)
#pragma unroll
        for (int q = 0; q < 4; q++) { acc[nt][q] = 0.0f; cmp[nt][q] = 0.0f; }

    // -------- prologue: chunk 0 --------
    {
        const unsigned wb = smem_u + OFF_W1;
#pragma unroll
        for (int p = 0; p < 3; p++)
            cp16(wb + p * WT_B + w_e * STR_B + w_seg * 16,
                 &g_ws[p * (E_DIM * D_DIM) + w_e * D_DIM + w_seg * 8]);
        cp_commit();
        float4 xr[4];
#pragma unroll
        for (int p = 0; p < 4; p++)
            xr[p] = *(const float4*)&x[(t0 + x_tok + 32 * p) * D_DIM + x_kq * 4];
#pragma unroll
        for (int p = 0; p < 4; p++)
            store_split_f4(smem, (uint32_t)((x_tok + 32 * p) * STR_B + x_kq * 8), xr[p]);
    }

    // -------- pipelined main loop: one bar per chunk --------
#pragma unroll 1
    for (int c = 0; c < NCHUNK; c++) {
        cp_wait<0>();          // W(c) landed (committed one iter ago)
        __syncthreads();       // all STS(c) + cp(c) visible; bufB free of readers

        char* bufA = smem + (c & 1) * BUF_B;
        char* bufB = smem + ((c + 1) & 1) * BUF_B;
        const uint32_t bufA_u = smem_u + (uint32_t)((c & 1) * BUF_B);

        float4 xr[4];
        const bool more = (c + 1 < NCHUNK);
        if (more) {
            const int k0n = (c + 1) * KC;
            const unsigned wb = smem_u + (uint32_t)(((c + 1) & 1) * BUF_B) + OFF_W1;
#pragma unroll
            for (int p = 0; p < 3; p++)
                cp16(wb + p * WT_B + w_e * STR_B + w_seg * 16,
                     &g_ws[p * (E_DIM * D_DIM) + w_e * D_DIM + k0n + w_seg * 8]);
            cp_commit();
#pragma unroll
            for (int p = 0; p < 4; p++)
                xr[p] = *(const float4*)&x[(t0 + x_tok + 32 * p) * D_DIM + k0n + x_kq * 4];
        }

        // ---- mma chunk c ----
        float cacc[4][4];
#pragma unroll
        for (int nt = 0; nt < 4; nt++)
#pragma unroll
            for (int q = 0; q < 4; q++) cacc[nt][q] = 0.0f;

#pragma unroll
        for (int ks = 0; ks < 4; ks++) {
            const uint32_t a_off = bufA_u + a_row_off + (uint32_t)ks * 32;
            uint32_t a1[4], a2[4], a3[4];
            ldm_x4(a1[0],a1[1],a1[2],a1[3], a_off + OFF_X1);
            ldm_x4(a2[0],a2[1],a2[2],a2[3], a_off + OFF_X2);
            ldm_x4(a3[0],a3[1],a3[2],a3[3], a_off + OFF_X3);
#pragma unroll
            for (int nt = 0; nt < 4; nt++) {
                const uint32_t b_off = bufA_u + b_row_off
                    + (uint32_t)(nt * 8) * STR_B + (uint32_t)ks * 32;
                uint32_t b1a,b1b,b2a,b2b,b3a,b3b;
                ldm_x2(b1a, b1b, b_off + OFF_W1);
                ldm_x2(b2a, b2b, b_off + OFF_W2);
                ldm_x2(b3a, b3b, b_off + OFF_W3);
                mma_bf16(cacc[nt], a1, b1a, b1b);   // x1*w1
                mma_bf16(cacc[nt], a1, b2a, b2b);   // x1*w2
                mma_bf16(cacc[nt], a2, b1a, b1b);   // x2*w1
                mma_bf16(cacc[nt], a1, b3a, b3b);   // x1*w3
                mma_bf16(cacc[nt], a2, b2a, b2b);   // x2*w2
                mma_bf16(cacc[nt], a3, b1a, b1b);   // x3*w1
            }
        }

        // Kahan-fold chunk sums
#pragma unroll
        for (int nt = 0; nt < 4; nt++)
#pragma unroll
            for (int q = 0; q < 4; q++) {
                float y = cacc[nt][q] - cmp[nt][q];
                float t = acc[nt][q] + y;
                cmp[nt][q] = (t - acc[nt][q]) - y;
                acc[nt][q] = t;
            }

        // ---- split + store x(c+1) into bufB ----
        if (more) {
#pragma unroll
            for (int p = 0; p < 4; p++)
                store_split_f4(bufB, (uint32_t)((x_tok + 32 * p) * STR_B + x_kq * 8), xr[p]);
        }
    }

    // ---------------- logits -> smem ----------------
    __syncthreads();
    float* logit = (float*)smem;
    {
        const int r0 = m_base + (lane >> 2);
        const int c0 = (lane & 3) * 2;
#pragma unroll
        for (int nt = 0; nt < 4; nt++) {
            const int col = eh * 32 + nt * 8 + c0;
            *(float2*)&logit[r0 * LOG_STR + col] = make_float2(acc[nt][0], acc[nt][1]);
            *(float2*)&logit[(r0 + 8) * LOG_STR + col] = make_float2(acc[nt][2], acc[nt][3]);
        }
    }
    __syncthreads();

    // ---------------- epilogue: softmax + top-8 + stats (proven) ------------
    const int et = tid & 15;      // expert lane (experts et + 16r)
    const int tt = tid >> 4;      // token thread 0..31 (tokens tt + 32j)

    float loc_ssum[4] = {0.0f, 0.0f, 0.0f, 0.0f};

#pragma unroll 1
    for (int j = 0; j < 4; j++) {
        const int token = tt + 32 * j;
        float a[4];
#pragma unroll
        for (int r = 0; r < 4; r++)
            a[r] = logit[token * LOG_STR + et + 16 * r];

        float m = a[0];
#pragma unroll
        for (int r = 1; r < 4; r++) m = fmaxf(m, a[r]);
#pragma unroll
        for (int d = 1; d < 16; d <<= 1)
            m = fmaxf(m, __shfl_xor_sync(fullmask, m, d));

        float sc[4];
        float s = 0.0f;
#pragma unroll
        for (int r = 0; r < 4; r++) { sc[r] = expf(a[r] - m); s += sc[r]; }
#pragma unroll
        for (int d = 1; d < 16; d <<= 1)
            s += __shfl_xor_sync(fullmask, s, d);
#pragma unroll
        for (int r = 0; r < 4; r++) { sc[r] = sc[r] / s; loc_ssum[r] += sc[r]; }

        float tv[TOPK]; int ti[TOPK];
#pragma unroll 1
        for (int it = 0; it < TOPK; it++) {
            float bv = -1.0f; int bi = E_DIM;
#pragma unroll
            for (int r = 0; r < 4; r++)
                if (sc[r] > bv) { bv = sc[r]; bi = et + 16 * r; }
#pragma unroll
            for (int d = 1; d < 16; d <<= 1) {
                float ov = __shfl_xor_sync(fullmask, bv, d);
                int   oi = __shfl_xor_sync(fullmask, bi, d);
                if (ov > bv || (ov == bv && oi < bi)) { bv = ov; bi = oi; }
            }
            if ((bi & 15) == et) sc[bi >> 4] = -1.0f;
            tv[it] = bv; ti[it] = bi;
        }

        if (et == 0) {
            float wsum = 0.0f;
#pragma unroll
            for (int it = 0; it < TOPK; it++) wsum += tv[it];
            wsum += EPS_R;
            long t = t0 + token;
#pragma unroll
            for (int it = 0; it < TOPK; it++) {
                out_idx[t * TOPK + it] = (float)ti[it];
                out_w  [t * TOPK + it] = tv[it] / wsum;
                atomicAdd(&sm_cnt[ti[it]], 1.0f);
            }
        }
    }

#pragma unroll
    for (int r = 0; r < 4; r++)
        atomicAdd(&sm_ssum[et + 16 * r], loc_ssum[r]);
    __syncthreads();

    if (tid < E_DIM) {
        int b = (int)(t0 / (long)S);
        atomicAdd(&g_ce[b * E_DIM + tid],   sm_cnt[tid]);
        atomicAdd(&g_ssum[b * E_DIM + tid], sm_ssum[tid]);
    }

    // ---------------- fused aux finalization (last CTA) ----------------
    __threadfence();
    if (tid == 0) sm_ticket = atomicAdd(&g_count, 1u);
    __syncthreads();

    if (sm_ticket == (unsigned)(nblocks - 1)) {
        __threadfence();
        const volatile float* ce = g_ce;
        const volatile float* ss = g_ssum;
        float v = (tid < B_DIM * E_DIM) ? ce[tid] * ss[tid] : 0.0f;
        float* red = (float*)smem;
        red[tid] = v;
        __syncthreads();
        for (int off = 256; off > 0; off >>= 1) {
            if (tid < off) red[tid] += red[tid + off];
            __syncthreads();
        }
        if (tid == 0)
            out_aux[0] = red[0] / (float)S / (float)B_DIM * ALPHA;
        if (tid < B_DIM * E_DIM) { g_ce[tid] = 0.0f; g_ssum[tid] = 0.0f; }
        if (tid == 0) g_count = 0u;
    }
}

extern "C" void kernel_launch(void* const* d_in, const int* in_sizes, int n_in,
                              void* d_out, int out_size) {
    const float* x = (const float*)d_in[0];
    const float* W = (const float*)d_in[1];
    const int T = in_sizes[0] / D_DIM;     // 32768
    const int S = T / B_DIM;               // 8192
    const int nblocks = T / TPB;           // 256

    float* out     = (float*)d_out;
    float* out_idx = out;                         // [T,8] indices as float
    float* out_w   = out + (size_t)T * TOPK;      // [T,8] weights
    float* out_aux = out + (out_size - 1);        // scalar aux loss

    wsplit_kernel<<<(E_DIM * D_DIM + 1023) / 1024, 1024>>>(W);

    cudaFuncSetAttribute(moe_gate_kernel,
                         cudaFuncAttributeMaxDynamicSharedMemorySize, SMEM_BYTES);
    moe_gate_kernel<<<nblocks, THREADS, SMEM_BYTES>>>(x, out_idx, out_w,
                                                      out_aux, S, nblocks);
}

// round 11
// speedup vs baseline: 1.5645x; 1.2846x over previous
#include <cuda_runtime.h>
#include <cuda_fp16.h>
#include <cstdint>

// Problem constants
#define D_DIM   1024
#define E_DIM   64
#define TOPK    8
#define B_DIM   4
#define ALPHA   0.1f
#define EPS_R   1e-20f

#define THREADS 512
#define TPB     128              // tokens per CTA
#define KC      64               // K per chunk
#define NCHUNK  (D_DIM / KC)     // 16

#define W_SCALE    65536.0f      // 2^16: keeps w2 split term normal in fp16
#define W_UNSCALE  1.52587890625e-05f   // 2^-16 (exact)

// smem: fp16 tiles, 64 cols used, row stride 72 el = 144 B (conflict-free ldmatrix)
#define STR_B   144
#define XT_B    (TPB * STR_B)         // 18432
#define WT_B    (E_DIM * STR_B)       // 9216
#define OFF_X1  0
#define OFF_X2  (OFF_X1 + XT_B)
#define OFF_W1  (OFF_X2 + XT_B)
#define OFF_W2  (OFF_W1 + WT_B)
#define BUF_B   (OFF_W2 + WT_B)       // 55296 per buffer
#define SMEM_BYTES (2 * BUF_B)        // 110592
#define LOG_STR 66                    // padded logits row (floats)

// device-global scratch (static — no allocation)
__device__ uint16_t g_ws[2 * E_DIM * D_DIM];   // pre-split scaled W (fp16 bits)
__device__ float g_ce[B_DIM * E_DIM];
__device__ float g_ssum[B_DIM * E_DIM];
__device__ unsigned int g_count;

// ------------------------- helpers -------------------------
// exact 2-way fp16 split (subtraction exact in fp32)
__device__ __forceinline__ void split2h(float v, uint32_t& a, uint32_t& b) {
    __half h1 = __float2half_rn(v);
    float r = v - __half2float(h1);
    __half h2 = __float2half_rn(r);
    a = __half_as_ushort(h1);
    b = __half_as_ushort(h2);
}

__device__ __forceinline__ void store_split_f4(char* sm, uint32_t byte_off, float4 v) {
    uint32_t a0,b0,a1,b1,a2,b2,a3,b3;
    split2h(v.x,a0,b0); split2h(v.y,a1,b1);
    split2h(v.z,a2,b2); split2h(v.w,a3,b3);
    *(uint2*)(sm + OFF_X1 + byte_off) = make_uint2(a0 | (a1 << 16), a2 | (a3 << 16));
    *(uint2*)(sm + OFF_X2 + byte_off) = make_uint2(b0 | (b1 << 16), b2 | (b3 << 16));
}

__device__ __forceinline__ void ldm_x4(uint32_t& r0, uint32_t& r1, uint32_t& r2,
                                       uint32_t& r3, uint32_t addr) {
    asm volatile("ldmatrix.sync.aligned.m8n8.x4.shared.b16 {%0,%1,%2,%3}, [%4];"
                 : "=r"(r0),"=r"(r1),"=r"(r2),"=r"(r3) : "r"(addr));
}
__device__ __forceinline__ void ldm_x2(uint32_t& r0, uint32_t& r1, uint32_t addr) {
    asm volatile("ldmatrix.sync.aligned.m8n8.x2.shared.b16 {%0,%1}, [%2];"
                 : "=r"(r0),"=r"(r1) : "r"(addr));
}

__device__ __forceinline__ void mma_f16(float* c, const uint32_t* a,
                                        uint32_t b0, uint32_t b1) {
    asm volatile(
        "mma.sync.aligned.m16n8k16.row.col.f32.f16.f16.f32 "
        "{%0,%1,%2,%3}, {%4,%5,%6,%7}, {%8,%9}, {%0,%1,%2,%3};"
        : "+f"(c[0]), "+f"(c[1]), "+f"(c[2]), "+f"(c[3])
        : "r"(a[0]), "r"(a[1]), "r"(a[2]), "r"(a[3]), "r"(b0), "r"(b1));
}

__device__ __forceinline__ void cp16(unsigned dst, const void* src) {
    asm volatile("cp.async.ca.shared.global [%0], [%1], 16;\n" :: "r"(dst), "l"(src));
}
__device__ __forceinline__ void cp_commit() {
    asm volatile("cp.async.commit_group;\n");
}
template <int N>
__device__ __forceinline__ void cp_wait() {
    asm volatile("cp.async.wait_group %0;\n" :: "n"(N));
}

// ------------------------- W pre-split kernel -------------------------
__global__ void wsplit_kernel(const float* __restrict__ W) {
    int i = blockIdx.x * blockDim.x + threadIdx.x;
    if (i < E_DIM * D_DIM) {
        uint32_t a, b;
        split2h(W[i] * W_SCALE, a, b);
        g_ws[i]                 = (uint16_t)a;
        g_ws[E_DIM * D_DIM + i] = (uint16_t)b;
    }
}

// ------------------------- main kernel -------------------------
__global__ __launch_bounds__(THREADS, 1)
void moe_gate_kernel(const float* __restrict__ x,
                     float* __restrict__ out_idx,
                     float* __restrict__ out_w,
                     float* __restrict__ out_aux,
                     int S, int nblocks)
{
    extern __shared__ char smem[];
    __shared__ float sm_cnt[E_DIM];
    __shared__ float sm_ssum[E_DIM];
    __shared__ unsigned int sm_ticket;

    const int tid  = threadIdx.x;
    const int wid  = tid >> 5;
    const int lane = tid & 31;
    const long t0  = (long)blockIdx.x * TPB;
    const unsigned fullmask = 0xffffffffu;

    const uint32_t smem_u = (uint32_t)__cvta_generic_to_shared(smem);

    // warp tile: 16 tokens x 32 experts
    const int tok_grp = wid >> 1;            // 0..7
    const int eh      = wid & 1;             // expert half (0/1)
    const int m_base  = tok_grp * 16;

    if (tid < E_DIM) { sm_cnt[tid] = 0.0f; sm_ssum[tid] = 0.0f; }

    // ldmatrix per-lane address components (validated rounds 9-10)
    const uint32_t a_row_off = (uint32_t)(m_base + (lane & 15)) * STR_B
                             + (uint32_t)(lane >> 4) * 16;
    const uint32_t b_row_off = (uint32_t)(lane & 7) * STR_B
                             + (uint32_t)((lane >> 3) & 1) * 16
                             + (uint32_t)(eh * 32) * STR_B;

    // per-thread load indices: x tile 2048 f4 / 512 thr = 4; W cp 1024 / 512 = 2
    const int x_kq  = tid & 15;          // float4 col
    const int x_tok = tid >> 4;          // +32p
    const int w_e   = tid >> 3;          // expert row (0..63)
    const int w_seg = tid & 7;           // 16B segment

    float acc[4][4], cmp[4][4];
#pragma unroll
    for (int nt = 0; nt < 4; nt++)
#pragma unroll
        for (int q = 0; q < 4; q++) { acc[nt][q] = 0.0f; cmp[nt][q] = 0.0f; }

    // -------- prologue: chunk 0 --------
    {
        const unsigned wb = smem_u + OFF_W1;
#pragma unroll
        for (int p = 0; p < 2; p++)
            cp16(wb + p * WT_B + w_e * STR_B + w_seg * 16,
                 &g_ws[p * (E_DIM * D_DIM) + w_e * D_DIM + w_seg * 8]);
        cp_commit();
        float4 xr[4];
#pragma unroll
        for (int p = 0; p < 4; p++)
            xr[p] = *(const float4*)&x[(t0 + x_tok + 32 * p) * D_DIM + x_kq * 4];
#pragma unroll
        for (int p = 0; p < 4; p++)
            store_split_f4(smem, (uint32_t)((x_tok + 32 * p) * STR_B + x_kq * 8), xr[p]);
    }

    // -------- pipelined main loop: one bar per chunk --------
#pragma unroll 1
    for (int c = 0; c < NCHUNK; c++) {
        cp_wait<0>();          // W(c) landed
        __syncthreads();       // STS(c)+cp(c) visible; next buffer free of readers

        char* bufB = smem + ((c + 1) & 1) * BUF_B;
        const uint32_t bufA_u = smem_u + (uint32_t)((c & 1) * BUF_B);

        float4 xr[4];
        const bool more = (c + 1 < NCHUNK);
        if (more) {
            const int k0n = (c + 1) * KC;
            const unsigned wb = smem_u + (uint32_t)(((c + 1) & 1) * BUF_B) + OFF_W1;
#pragma unroll
            for (int p = 0; p < 2; p++)
                cp16(wb + p * WT_B + w_e * STR_B + w_seg * 16,
                     &g_ws[p * (E_DIM * D_DIM) + w_e * D_DIM + k0n + w_seg * 8]);
            cp_commit();
#pragma unroll
            for (int p = 0; p < 4; p++)
                xr[p] = *(const float4*)&x[(t0 + x_tok + 32 * p) * D_DIM + k0n + x_kq * 4];
        }

        // ---- mma chunk c: 4 fp16 products ----
        float cacc[4][4];
#pragma unroll
        for (int nt = 0; nt < 4; nt++)
#pragma unroll
            for (int q = 0; q < 4; q++) cacc[nt][q] = 0.0f;

#pragma unroll
        for (int ks = 0; ks < 4; ks++) {
            const uint32_t a_off = bufA_u + a_row_off + (uint32_t)ks * 32;
            uint32_t a1[4], a2[4];
            ldm_x4(a1[0],a1[1],a1[2],a1[3], a_off + OFF_X1);
            ldm_x4(a2[0],a2[1],a2[2],a2[3], a_off + OFF_X2);
#pragma unroll
            for (int nt = 0; nt < 4; nt++) {
                const uint32_t b_off = bufA_u + b_row_off
                    + (uint32_t)(nt * 8) * STR_B + (uint32_t)ks * 32;
                uint32_t b1a,b1b,b2a,b2b;
                ldm_x2(b1a, b1b, b_off + OFF_W1);
                ldm_x2(b2a, b2b, b_off + OFF_W2);
                mma_f16(cacc[nt], a1, b1a, b1b);   // x1*w1
                mma_f16(cacc[nt], a1, b2a, b2b);   // x1*w2
                mma_f16(cacc[nt], a2, b1a, b1b);   // x2*w1
                mma_f16(cacc[nt], a2, b2a, b2b);   // x2*w2
            }
        }

        // Kahan-fold chunk sums
#pragma unroll
        for (int nt = 0; nt < 4; nt++)
#pragma unroll
            for (int q = 0; q < 4; q++) {
                float y = cacc[nt][q] - cmp[nt][q];
                float t = acc[nt][q] + y;
                cmp[nt][q] = (t - acc[nt][q]) - y;
                acc[nt][q] = t;
            }

        // ---- split + store x(c+1) into next buffer ----
        if (more) {
#pragma unroll
            for (int p = 0; p < 4; p++)
                store_split_f4(bufB, (uint32_t)((x_tok + 32 * p) * STR_B + x_kq * 8), xr[p]);
        }
    }

    // ---------------- logits -> smem (unscale by 2^-16, exact) ----------------
    __syncthreads();
    float* logit = (float*)smem;
    {
        const int r0 = m_base + (lane >> 2);
        const int c0 = (lane & 3) * 2;
#pragma unroll
        for (int nt = 0; nt < 4; nt++) {
            const int col = eh * 32 + nt * 8 + c0;
            *(float2*)&logit[r0 * LOG_STR + col] =
                make_float2(acc[nt][0] * W_UNSCALE, acc[nt][1] * W_UNSCALE);
            *(float2*)&logit[(r0 + 8) * LOG_STR + col] =
                make_float2(acc[nt][2] * W_UNSCALE, acc[nt][3] * W_UNSCALE);
        }
    }
    __syncthreads();

    // ---------------- epilogue: softmax + top-8 + stats (proven) ------------
    const int et = tid & 15;      // expert lane (experts et + 16r)
    const int tt = tid >> 4;      // token thread 0..31 (tokens tt + 32j)

    float loc_ssum[4] = {0.0f, 0.0f, 0.0f, 0.0f};

#pragma unroll 1
    for (int j = 0; j < 4; j++) {
        const int token = tt + 32 * j;
        float a[4];
#pragma unroll
        for (int r = 0; r < 4; r++)
            a[r] = logit[token * LOG_STR + et + 16 * r];

        float m = a[0];
#pragma unroll
        for (int r = 1; r < 4; r++) m = fmaxf(m, a[r]);
#pragma unroll
        for (int d = 1; d < 16; d <<= 1)
            m = fmaxf(m, __shfl_xor_sync(fullmask, m, d));

        float sc[4];
        float s = 0.0f;
#pragma unroll
        for (int r = 0; r < 4; r++) { sc[r] = expf(a[r] - m); s += sc[r]; }
#pragma unroll
        for (int d = 1; d < 16; d <<= 1)
            s += __shfl_xor_sync(fullmask, s, d);
#pragma unroll
        for (int r = 0; r < 4; r++) { sc[r] = sc[r] / s; loc_ssum[r] += sc[r]; }

        float tv[TOPK]; int ti[TOPK];
#pragma unroll 1
        for (int it = 0; it < TOPK; it++) {
            float bv = -1.0f; int bi = E_DIM;
#pragma unroll
            for (int r = 0; r < 4; r++)
                if (sc[r] > bv) { bv = sc[r]; bi = et + 16 * r; }
#pragma unroll
            for (int d = 1; d < 16; d <<= 1) {
                float ov = __shfl_xor_sync(fullmask, bv, d);
                int   oi = __shfl_xor_sync(fullmask, bi, d);
                if (ov > bv || (ov == bv && oi < bi)) { bv = ov; bi = oi; }
            }
            if ((bi & 15) == et) sc[bi >> 4] = -1.0f;
            tv[it] = bv; ti[it] = bi;
        }

        if (et == 0) {
            float wsum = 0.0f;
#pragma unroll
            for (int it = 0; it < TOPK; it++) wsum += tv[it];
            wsum += EPS_R;
            long t = t0 + token;
#pragma unroll
            for (int it = 0; it < TOPK; it++) {
                out_idx[t * TOPK + it] = (float)ti[it];
                out_w  [t * TOPK + it] = tv[it] / wsum;
                atomicAdd(&sm_cnt[ti[it]], 1.0f);
            }
        }
    }

#pragma unroll
    for (int r = 0; r < 4; r++)
        atomicAdd(&sm_ssum[et + 16 * r], loc_ssum[r]);
    __syncthreads();

    if (tid < E_DIM) {
        int b = (int)(t0 / (long)S);
        atomicAdd(&g_ce[b * E_DIM + tid],   sm_cnt[tid]);
        atomicAdd(&g_ssum[b * E_DIM + tid], sm_ssum[tid]);
    }

    // ---------------- fused aux finalization (last CTA) ----------------
    __threadfence();
    if (tid == 0) sm_ticket = atomicAdd(&g_count, 1u);
    __syncthreads();

    if (sm_ticket == (unsigned)(nblocks - 1)) {
        __threadfence();
        const volatile float* ce = g_ce;
        const volatile float* ss = g_ssum;
        float v = (tid < B_DIM * E_DIM) ? ce[tid] * ss[tid] : 0.0f;
        float* red = (float*)smem;
        red[tid] = v;
        __syncthreads();
        for (int off = 256; off > 0; off >>= 1) {
            if (tid < off) red[tid] += red[tid + off];
            __syncthreads();
        }
        if (tid == 0)
            out_aux[0] = red[0] / (float)S / (float)B_DIM * ALPHA;
        if (tid < B_DIM * E_DIM) { g_ce[tid] = 0.0f; g_ssum[tid] = 0.0f; }
        if (tid == 0) g_count = 0u;
    }
}

extern "C" void kernel_launch(void* const* d_in, const int* in_sizes, int n_in,
                              void* d_out, int out_size) {
    const float* x = (const float*)d_in[0];
    const float* W = (const float*)d_in[1];
    const int T = in_sizes[0] / D_DIM;     // 32768
    const int S = T / B_DIM;               // 8192
    const int nblocks = T / TPB;           // 256

    float* out     = (float*)d_out;
    float* out_idx = out;                         // [T,8] indices as float
    float* out_w   = out + (size_t)T * TOPK;      // [T,8] weights
    float* out_aux = out + (out_size - 1);        // scalar aux loss

    wsplit_kernel<<<(E_DIM * D_DIM + 1023) / 1024, 1024>>>(W);

    cudaFuncSetAttribute(moe_gate_kernel,
                         cudaFuncAttributeMaxDynamicSharedMemorySize, SMEM_BYTES);
    moe_gate_kernel<<<nblocks, THREADS, SMEM_BYTES>>>(x, out_idx, out_w,
                                                      out_aux, S, nblocks);
}

// round 12
// speedup vs baseline: 1.6181x; 1.0342x over previous
#include <cuda_runtime.h>
#include <cuda_fp16.h>
#include <cstdint>

// Problem constants
#define D_DIM   1024
#define E_DIM   64
#define TOPK    8
#define B_DIM   4
#define ALPHA   0.1f
#define EPS_R   1e-20f

#define THREADS 256
#define TPB     64               // tokens per tile
#define NTILES  2                // tiles per CTA (persistent)
#define KC      64               // K per chunk
#define NCHUNK  (D_DIM / KC)     // 16

#define W_SCALE    65536.0f      // 2^16: keeps w2 split term normal in fp16
#define W_UNSCALE  1.52587890625e-05f   // 2^-16 (exact)

// smem: fp16 tiles, 64 cols used, row stride 72 el = 144 B (conflict-free ldmatrix)
#define STR_B   144
#define XT_B    (TPB * STR_B)         // 9216
#define WT_B    (E_DIM * STR_B)       // 9216
#define OFF_X1  0
#define OFF_X2  (OFF_X1 + XT_B)
#define OFF_W1  (OFF_X2 + XT_B)
#define OFF_W2  (OFF_W1 + WT_B)
#define BUF_B   (OFF_W2 + WT_B)       // 36864 per buffer
#define SMEM_BYTES (2 * BUF_B)        // 73728 per CTA (x2 CTA/SM = 144KB)
#define LOG_STR 66                    // padded logits row (floats)

// device-global scratch (static — no allocation)
__device__ uint16_t g_ws[2 * E_DIM * D_DIM];   // pre-split scaled W (fp16 bits)
__device__ float g_ce[B_DIM * E_DIM];
__device__ float g_ssum[B_DIM * E_DIM];
__device__ unsigned int g_count;

// ------------------------- helpers -------------------------
__device__ __forceinline__ void split2h(float v, uint32_t& a, uint32_t& b) {
    __half h1 = __float2half_rn(v);
    float r = v - __half2float(h1);
    __half h2 = __float2half_rn(r);
    a = __half_as_ushort(h1);
    b = __half_as_ushort(h2);
}

__device__ __forceinline__ void store_split_f4(char* sm, uint32_t byte_off, float4 v) {
    uint32_t a0,b0,a1,b1,a2,b2,a3,b3;
    split2h(v.x,a0,b0); split2h(v.y,a1,b1);
    split2h(v.z,a2,b2); split2h(v.w,a3,b3);
    *(uint2*)(sm + OFF_X1 + byte_off) = make_uint2(a0 | (a1 << 16), a2 | (a3 << 16));
    *(uint2*)(sm + OFF_X2 + byte_off) = make_uint2(b0 | (b1 << 16), b2 | (b3 << 16));
}

__device__ __forceinline__ void ldm_x4(uint32_t& r0, uint32_t& r1, uint32_t& r2,
                                       uint32_t& r3, uint32_t addr) {
    asm volatile("ldmatrix.sync.aligned.m8n8.x4.shared.b16 {%0,%1,%2,%3}, [%4];"
                 : "=r"(r0),"=r"(r1),"=r"(r2),"=r"(r3) : "r"(addr));
}

__device__ __forceinline__ void mma_f16(float* c, const uint32_t* a,
                                        uint32_t b0, uint32_t b1) {
    asm volatile(
        "mma.sync.aligned.m16n8k16.row.col.f32.f16.f16.f32 "
        "{%0,%1,%2,%3}, {%4,%5,%6,%7}, {%8,%9}, {%0,%1,%2,%3};"
        : "+f"(c[0]), "+f"(c[1]), "+f"(c[2]), "+f"(c[3])
        : "r"(a[0]), "r"(a[1]), "r"(a[2]), "r"(a[3]), "r"(b0), "r"(b1));
}

__device__ __forceinline__ void cp16(unsigned dst, const void* src) {
    asm volatile("cp.async.ca.shared.global [%0], [%1], 16;\n" :: "r"(dst), "l"(src));
}
__device__ __forceinline__ void cp_commit() {
    asm volatile("cp.async.commit_group;\n");
}
template <int N>
__device__ __forceinline__ void cp_wait() {
    asm volatile("cp.async.wait_group %0;\n" :: "n"(N));
}

// ------------------------- W pre-split kernel -------------------------
__global__ void wsplit_kernel(const float* __restrict__ W) {
    int i = blockIdx.x * blockDim.x + threadIdx.x;
    if (i < E_DIM * D_DIM) {
        uint32_t a, b;
        split2h(W[i] * W_SCALE, a, b);
        g_ws[i]                 = (uint16_t)a;
        g_ws[E_DIM * D_DIM + i] = (uint16_t)b;
    }
}

// ------------------------- main kernel -------------------------
__global__ __launch_bounds__(THREADS, 2)
void moe_gate_kernel(const float* __restrict__ x,
                     float* __restrict__ out_idx,
                     float* __restrict__ out_w,
                     float* __restrict__ out_aux,
                     int S, int nblocks)
{
    extern __shared__ char smem[];
    __shared__ float sm_cnt[E_DIM];
    __shared__ float sm_ssum[E_DIM];
    __shared__ unsigned int sm_ticket;

    const int tid  = threadIdx.x;
    const int wid  = tid >> 5;
    const int lane = tid & 31;
    const unsigned fullmask = 0xffffffffu;

    const uint32_t smem_u = (uint32_t)__cvta_generic_to_shared(smem);

    // warp tile: 16 tokens x 32 experts (4 token groups x 2 expert halves)
    const int tok_grp = wid >> 1;            // 0..3
    const int eh      = wid & 1;             // expert half (0/1)
    const int m_base  = tok_grp * 16;

    // A ldmatrix per-lane address (validated rounds 9-11)
    const uint32_t a_row_off = (uint32_t)(m_base + (lane & 15)) * STR_B
                             + (uint32_t)(lane >> 4) * 16;
    // B paired-x4 per-lane address: matrices [nt0 k0][nt0 k1][nt1 k0][nt1 k1]
    const uint32_t b4_off = (uint32_t)((lane & 7) + ((lane >> 4) & 1) * 8
                                       + eh * 32) * STR_B
                          + (uint32_t)((lane >> 3) & 1) * 16;

    // x tile loads: 64 tok x 16 f4 = 1024 f4 -> 4/thread
    const int x_kq  = tid & 15;
    const int x_tok = tid >> 4;          // + 16p

    float loc_ssum_all[4] = {0.f, 0.f, 0.f, 0.f};
    if (tid < E_DIM) { sm_cnt[tid] = 0.0f; sm_ssum[tid] = 0.0f; }
    __syncthreads();

#pragma unroll 1
    for (int tile = 0; tile < NTILES; tile++) {
        const long t0 = (long)(blockIdx.x + tile * nblocks) * TPB;

        float acc[4][4], cmp[4][4];
#pragma unroll
        for (int nt = 0; nt < 4; nt++)
#pragma unroll
            for (int q = 0; q < 4; q++) { acc[nt][q] = 0.0f; cmp[nt][q] = 0.0f; }

        // -------- prologue: chunk 0 --------
        {
            // W: 2 planes x 64 e x 8 seg = 1024 cp16 -> 4/thread
#pragma unroll
            for (int p = 0; p < 4; p++) {
                int idx = tid + THREADS * p;
                int pl = idx >> 9, rem = idx & 511;
                int e = rem >> 3, seg = rem & 7;
                cp16(smem_u + OFF_W1 + pl * WT_B + e * STR_B + seg * 16,
                     &g_ws[pl * (E_DIM * D_DIM) + e * D_DIM + seg * 8]);
            }
            cp_commit();
            float4 xr[4];
#pragma unroll
            for (int p = 0; p < 4; p++)
                xr[p] = *(const float4*)&x[(t0 + x_tok + 16 * p) * D_DIM + x_kq * 4];
#pragma unroll
            for (int p = 0; p < 4; p++)
                store_split_f4(smem, (uint32_t)((x_tok + 16 * p) * STR_B + x_kq * 8), xr[p]);
        }

        // -------- pipelined main loop: one bar per chunk --------
#pragma unroll 1
        for (int c = 0; c < NCHUNK; c++) {
            cp_wait<0>();
            __syncthreads();

            char* bufB = smem + ((c + 1) & 1) * BUF_B;
            const uint32_t bufA_u = smem_u + (uint32_t)((c & 1) * BUF_B);

            float4 xr[4];
            const bool more = (c + 1 < NCHUNK);
            if (more) {
                const int k0n = (c + 1) * KC;
                const unsigned wb = smem_u + (uint32_t)(((c + 1) & 1) * BUF_B) + OFF_W1;
#pragma unroll
                for (int p = 0; p < 4; p++) {
                    int idx = tid + THREADS * p;
                    int pl = idx >> 9, rem = idx & 511;
                    int e = rem >> 3, seg = rem & 7;
                    cp16(wb + pl * WT_B + e * STR_B + seg * 16,
                         &g_ws[pl * (E_DIM * D_DIM) + e * D_DIM + k0n + seg * 8]);
                }
                cp_commit();
#pragma unroll
                for (int p = 0; p < 4; p++)
                    xr[p] = *(const float4*)&x[(t0 + x_tok + 16 * p) * D_DIM + k0n + x_kq * 4];
            }

            // ---- mma chunk c: 4 fp16 products, B loaded as paired x4 ----
            float cacc[4][4];
#pragma unroll
            for (int nt = 0; nt < 4; nt++)
#pragma unroll
                for (int q = 0; q < 4; q++) cacc[nt][q] = 0.0f;

#pragma unroll
            for (int ks = 0; ks < 4; ks++) {
                const uint32_t a_off = bufA_u + a_row_off + (uint32_t)ks * 32;
                uint32_t a1[4], a2[4];
                ldm_x4(a1[0],a1[1],a1[2],a1[3], a_off + OFF_X1);
                ldm_x4(a2[0],a2[1],a2[2],a2[3], a_off + OFF_X2);
#pragma unroll
                for (int ntp = 0; ntp < 2; ntp++) {
                    const uint32_t b_off = bufA_u + b4_off
                        + (uint32_t)(ntp * 16) * STR_B + (uint32_t)ks * 32;
                    uint32_t w1[4], w2[4];
                    ldm_x4(w1[0],w1[1],w1[2],w1[3], b_off + OFF_W1);
                    ldm_x4(w2[0],w2[1],w2[2],w2[3], b_off + OFF_W2);
#pragma unroll
                    for (int h = 0; h < 2; h++) {
                        const int nt = ntp * 2 + h;
                        mma_f16(cacc[nt], a1, w1[2*h], w1[2*h+1]);   // x1*w1
                        mma_f16(cacc[nt], a1, w2[2*h], w2[2*h+1]);   // x1*w2
                        mma_f16(cacc[nt], a2, w1[2*h], w1[2*h+1]);   // x2*w1
                        mma_f16(cacc[nt], a2, w2[2*h], w2[2*h+1]);   // x2*w2
                    }
                }
            }

            // Kahan-fold chunk sums
#pragma unroll
            for (int nt = 0; nt < 4; nt++)
#pragma unroll
                for (int q = 0; q < 4; q++) {
                    float y = cacc[nt][q] - cmp[nt][q];
                    float t = acc[nt][q] + y;
                    cmp[nt][q] = (t - acc[nt][q]) - y;
                    acc[nt][q] = t;
                }

            // ---- split + store x(c+1) into next buffer ----
            if (more) {
#pragma unroll
                for (int p = 0; p < 4; p++)
                    store_split_f4(bufB, (uint32_t)((x_tok + 16 * p) * STR_B + x_kq * 8), xr[p]);
            }
        }

        // ---------------- logits -> smem (unscale 2^-16) ----------------
        __syncthreads();
        float* logit = (float*)smem;
        {
            const int r0 = m_base + (lane >> 2);
            const int c0 = (lane & 3) * 2;
#pragma unroll
            for (int nt = 0; nt < 4; nt++) {
                const int col = eh * 32 + nt * 8 + c0;
                *(float2*)&logit[r0 * LOG_STR + col] =
                    make_float2(acc[nt][0] * W_UNSCALE, acc[nt][1] * W_UNSCALE);
                *(float2*)&logit[(r0 + 8) * LOG_STR + col] =
                    make_float2(acc[nt][2] * W_UNSCALE, acc[nt][3] * W_UNSCALE);
            }
        }
        __syncthreads();

        // ---------------- epilogue: softmax + top-8 + stats ----------------
        const int et = tid & 15;      // expert lane (experts et + 16r)
        const int tt = tid >> 4;      // token thread 0..15 (tokens tt + 16j)

#pragma unroll 1
        for (int j = 0; j < 4; j++) {
            const int token = tt + 16 * j;
            float a[4];
#pragma unroll
            for (int r = 0; r < 4; r++)
                a[r] = logit[token * LOG_STR + et + 16 * r];

            float m = a[0];
#pragma unroll
            for (int r = 1; r < 4; r++) m = fmaxf(m, a[r]);
#pragma unroll
            for (int d = 1; d < 16; d <<= 1)
                m = fmaxf(m, __shfl_xor_sync(fullmask, m, d));

            float sc[4];
            float s = 0.0f;
#pragma unroll
            for (int r = 0; r < 4; r++) { sc[r] = expf(a[r] - m); s += sc[r]; }
#pragma unroll
            for (int d = 1; d < 16; d <<= 1)
                s += __shfl_xor_sync(fullmask, s, d);
#pragma unroll
            for (int r = 0; r < 4; r++) { sc[r] = sc[r] / s; loc_ssum_all[r] += sc[r]; }

            float tv[TOPK]; int ti[TOPK];
#pragma unroll 1
            for (int it = 0; it < TOPK; it++) {
                float bv = -1.0f; int bi = E_DIM;
#pragma unroll
                for (int r = 0; r < 4; r++)
                    if (sc[r] > bv) { bv = sc[r]; bi = et + 16 * r; }
#pragma unroll
                for (int d = 1; d < 16; d <<= 1) {
                    float ov = __shfl_xor_sync(fullmask, bv, d);
                    int   oi = __shfl_xor_sync(fullmask, bi, d);
                    if (ov > bv || (ov == bv && oi < bi)) { bv = ov; bi = oi; }
                }
                if ((bi & 15) == et) sc[bi >> 4] = -1.0f;
                tv[it] = bv; ti[it] = bi;
            }

            if (et == 0) {
                float wsum = 0.0f;
#pragma unroll
                for (int it = 0; it < TOPK; it++) wsum += tv[it];
                wsum += EPS_R;
                long t = t0 + token;
#pragma unroll
                for (int it = 0; it < TOPK; it++) {
                    out_idx[t * TOPK + it] = (float)ti[it];
                    out_w  [t * TOPK + it] = tv[it] / wsum;
                    atomicAdd(&sm_cnt[ti[it]], 1.0f);
                }
            }
        }
        __syncthreads();   // logit buffer free before next tile's prologue
    }

    // per-thread score sums -> block stats (both tiles share batch b below)
    const int et = tid & 15;
#pragma unroll
    for (int r = 0; r < 4; r++)
        atomicAdd(&sm_ssum[et + 16 * r], loc_ssum_all[r]);
    __syncthreads();

    // NOTE: both tiles of this CTA lie in the same batch iff nblocks*TPB | S.
    // nblocks=256, TPB=64: tile0 token t0=bid*64, tile1 t0=(bid+256)*64.
    // bid*64/8192 and (bid+256)*64/8192 differ -> must split stats per tile.
    // We handled ssum jointly ONLY if batches match; they don't. So instead:
    // fold cnt/ssum per tile above would be needed — but sm_cnt adds happened
    // per-tile into shared. To stay correct, recompute batch per tile half:
    // tile0 tokens [bid*64, ...), tile1 [(bid+256)*64, ...). Both stats were
    // merged in sm_cnt/sm_ssum. Since bid in [0,256): tile0 batch = bid/128,
    // tile1 batch = (bid+256)/128 = bid/128 + 2. Split: we add HALF the merged
    // stats to each batch — WRONG. Fix: per-tile flush below.
    if (tid < E_DIM) {
        // merged stats are incorrect to split post-hoc; flushed per tile instead
    }

    // ---------------- fused aux finalization (last CTA) ----------------
    __threadfence();
    if (tid == 0) sm_ticket = atomicAdd(&g_count, 1u);
    __syncthreads();

    if (sm_ticket == (unsigned)(nblocks - 1)) {
        __threadfence();
        const volatile float* ce = g_ce;
        const volatile float* ss = g_ssum;
        float v = (tid < B_DIM * E_DIM) ? ce[tid] * ss[tid] : 0.0f;
        float* red = (float*)smem;
        red[tid] = v;
        __syncthreads();
        for (int off = 128; off > 0; off >>= 1) {
            if (tid < off) red[tid] += red[tid + off];
            __syncthreads();
        }
        if (tid == 0)
            out_aux[0] = red[0] / (float)S / (float)B_DIM * ALPHA;
        if (tid < B_DIM * E_DIM) { g_ce[tid] = 0.0f; g_ssum[tid] = 0.0f; }
        if (tid == 0) g_count = 0u;
    }
}

// Per-tile stats flush is required because a CTA's two tiles live in different
// batches. Simplest correct scheme: flush sm_cnt/sm_ssum to globals INSIDE the
// tile loop. Implemented via this wrapper to keep the hot loop clean:
// (we re-declare the kernel body above accordingly — the per-tile flush is in
// the epilogue path: sm_cnt accumulation and this flush, then reset.)

extern "C" void kernel_launch(void* const* d_in, const int* in_sizes, int n_in,
                              void* d_out, int out_size);

// -- corrected kernel: per-tile stat flush --
__global__ __launch_bounds__(THREADS, 2)
void moe_gate_kernel2(const float* __restrict__ x,
                      float* __restrict__ out_idx,
                      float* __restrict__ out_w,
                      float* __restrict__ out_aux,
                      int S, int nblocks)
{
    extern __shared__ char smem[];
    __shared__ float sm_cnt[E_DIM];
    __shared__ float sm_ssum[E_DIM];
    __shared__ unsigned int sm_ticket;

    const int tid  = threadIdx.x;
    const int wid  = tid >> 5;
    const int lane = tid & 31;
    const unsigned fullmask = 0xffffffffu;
    const uint32_t smem_u = (uint32_t)__cvta_generic_to_shared(smem);

    const int tok_grp = wid >> 1;
    const int eh      = wid & 1;
    const int m_base  = tok_grp * 16;

    const uint32_t a_row_off = (uint32_t)(m_base + (lane & 15)) * STR_B
                             + (uint32_t)(lane >> 4) * 16;
    const uint32_t b4_off = (uint32_t)((lane & 7) + ((lane >> 4) & 1) * 8
                                       + eh * 32) * STR_B
                          + (uint32_t)((lane >> 3) & 1) * 16;

    const int x_kq  = tid & 15;
    const int x_tok = tid >> 4;

#pragma unroll 1
    for (int tile = 0; tile < NTILES; tile++) {
        const long t0 = (long)(blockIdx.x + tile * nblocks) * TPB;

        if (tid < E_DIM) { sm_cnt[tid] = 0.0f; sm_ssum[tid] = 0.0f; }

        float acc[4][4], cmp[4][4];
#pragma unroll
        for (int nt = 0; nt < 4; nt++)
#pragma unroll
            for (int q = 0; q < 4; q++) { acc[nt][q] = 0.0f; cmp[nt][q] = 0.0f; }

        {
#pragma unroll
            for (int p = 0; p < 4; p++) {
                int idx = tid + THREADS * p;
                int pl = idx >> 9, rem = idx & 511;
                int e = rem >> 3, seg = rem & 7;
                cp16(smem_u + OFF_W1 + pl * WT_B + e * STR_B + seg * 16,
                     &g_ws[pl * (E_DIM * D_DIM) + e * D_DIM + seg * 8]);
            }
            cp_commit();
            float4 xr[4];
#pragma unroll
            for (int p = 0; p < 4; p++)
                xr[p] = *(const float4*)&x[(t0 + x_tok + 16 * p) * D_DIM + x_kq * 4];
#pragma unroll
            for (int p = 0; p < 4; p++)
                store_split_f4(smem, (uint32_t)((x_tok + 16 * p) * STR_B + x_kq * 8), xr[p]);
        }

#pragma unroll 1
        for (int c = 0; c < NCHUNK; c++) {
            cp_wait<0>();
            __syncthreads();

            char* bufB = smem + ((c + 1) & 1) * BUF_B;
            const uint32_t bufA_u = smem_u + (uint32_t)((c & 1) * BUF_B);

            float4 xr[4];
            const bool more = (c + 1 < NCHUNK);
            if (more) {
                const int k0n = (c + 1) * KC;
                const unsigned wb = smem_u + (uint32_t)(((c + 1) & 1) * BUF_B) + OFF_W1;
#pragma unroll
                for (int p = 0; p < 4; p++) {
                    int idx = tid + THREADS * p;
                    int pl = idx >> 9, rem = idx & 511;
                    int e = rem >> 3, seg = rem & 7;
                    cp16(wb + pl * WT_B + e * STR_B + seg * 16,
                         &g_ws[pl * (E_DIM * D_DIM) + e * D_DIM + k0n + seg * 8]);
                }
                cp_commit();
#pragma unroll
                for (int p = 0; p < 4; p++)
                    xr[p] = *(const float4*)&x[(t0 + x_tok + 16 * p) * D_DIM + k0n + x_kq * 4];
            }

            float cacc[4][4];
#pragma unroll
            for (int nt = 0; nt < 4; nt++)
#pragma unroll
                for (int q = 0; q < 4; q++) cacc[nt][q] = 0.0f;

#pragma unroll
            for (int ks = 0; ks < 4; ks++) {
                const uint32_t a_off = bufA_u + a_row_off + (uint32_t)ks * 32;
                uint32_t a1[4], a2[4];
                ldm_x4(a1[0],a1[1],a1[2],a1[3], a_off + OFF_X1);
                ldm_x4(a2[0],a2[1],a2[2],a2[3], a_off + OFF_X2);
#pragma unroll
                for (int ntp = 0; ntp < 2; ntp++) {
                    const uint32_t b_off = bufA_u + b4_off
                        + (uint32_t)(ntp * 16) * STR_B + (uint32_t)ks * 32;
                    uint32_t w1[4], w2[4];
                    ldm_x4(w1[0],w1[1],w1[2],w1[3], b_off + OFF_W1);
                    ldm_x4(w2[0],w2[1],w2[2],w2[3], b_off + OFF_W2);
#pragma unroll
                    for (int h = 0; h < 2; h++) {
                        const int nt = ntp * 2 + h;
                        mma_f16(cacc[nt], a1, w1[2*h], w1[2*h+1]);
                        mma_f16(cacc[nt], a1, w2[2*h], w2[2*h+1]);
                        mma_f16(cacc[nt], a2, w1[2*h], w1[2*h+1]);
                        mma_f16(cacc[nt], a2, w2[2*h], w2[2*h+1]);
                    }
                }
            }

#pragma unroll
            for (int nt = 0; nt < 4; nt++)
#pragma unroll
                for (int q = 0; q < 4; q++) {
                    float y = cacc[nt][q] - cmp[nt][q];
                    float t = acc[nt][q] + y;
                    cmp[nt][q] = (t - acc[nt][q]) - y;
                    acc[nt][q] = t;
                }

            if (more) {
#pragma unroll
                for (int p = 0; p < 4; p++)
                    store_split_f4(bufB, (uint32_t)((x_tok + 16 * p) * STR_B + x_kq * 8), xr[p]);
            }
        }

        __syncthreads();
        float* logit = (float*)smem;
        {
            const int r0 = m_base + (lane >> 2);
            const int c0 = (lane & 3) * 2;
#pragma unroll
            for (int nt = 0; nt < 4; nt++) {
                const int col = eh * 32 + nt * 8 + c0;
                *(float2*)&logit[r0 * LOG_STR + col] =
                    make_float2(acc[nt][0] * W_UNSCALE, acc[nt][1] * W_UNSCALE);
                *(float2*)&logit[(r0 + 8) * LOG_STR + col] =
                    make_float2(acc[nt][2] * W_UNSCALE, acc[nt][3] * W_UNSCALE);
            }
        }
        __syncthreads();

        const int et = tid & 15;
        const int tt = tid >> 4;
        float loc_ssum[4] = {0.f, 0.f, 0.f, 0.f};

#pragma unroll 1
        for (int j = 0; j < 4; j++) {
            const int token = tt + 16 * j;
            float a[4];
#pragma unroll
            for (int r = 0; r < 4; r++)
                a[r] = logit[token * LOG_STR + et + 16 * r];

            float m = a[0];
#pragma unroll
            for (int r = 1; r < 4; r++) m = fmaxf(m, a[r]);
#pragma unroll
            for (int d = 1; d < 16; d <<= 1)
                m = fmaxf(m, __shfl_xor_sync(fullmask, m, d));

            float sc[4];
            float s = 0.0f;
#pragma unroll
            for (int r = 0; r < 4; r++) { sc[r] = expf(a[r] - m); s += sc[r]; }
#pragma unroll
            for (int d = 1; d < 16; d <<= 1)
                s += __shfl_xor_sync(fullmask, s, d);
#pragma unroll
            for (int r = 0; r < 4; r++) { sc[r] = sc[r] / s; loc_ssum[r] += sc[r]; }

            float tv[TOPK]; int ti[TOPK];
#pragma unroll 1
            for (int it = 0; it < TOPK; it++) {
                float bv = -1.0f; int bi = E_DIM;
#pragma unroll
                for (int r = 0; r < 4; r++)
                    if (sc[r] > bv) { bv = sc[r]; bi = et + 16 * r; }
#pragma unroll
                for (int d = 1; d < 16; d <<= 1) {
                    float ov = __shfl_xor_sync(fullmask, bv, d);
                    int   oi = __shfl_xor_sync(fullmask, bi, d);
                    if (ov > bv || (ov == bv && oi < bi)) { bv = ov; bi = oi; }
                }
                if ((bi & 15) == et) sc[bi >> 4] = -1.0f;
                tv[it] = bv; ti[it] = bi;
            }

            if (et == 0) {
                float wsum = 0.0f;
#pragma unroll
                for (int it = 0; it < TOPK; it++) wsum += tv[it];
                wsum += EPS_R;
                long t = t0 + token;
#pragma unroll
                for (int it = 0; it < TOPK; it++) {
                    out_idx[t * TOPK + it] = (float)ti[it];
                    out_w  [t * TOPK + it] = tv[it] / wsum;
                    atomicAdd(&sm_cnt[ti[it]], 1.0f);
                }
            }
        }

#pragma unroll
        for (int r = 0; r < 4; r++)
            atomicAdd(&sm_ssum[et + 16 * r], loc_ssum[r]);
        __syncthreads();

        if (tid < E_DIM) {
            int b = (int)(t0 / (long)S);     // per-tile batch
            atomicAdd(&g_ce[b * E_DIM + tid],   sm_cnt[tid]);
            atomicAdd(&g_ssum[b * E_DIM + tid], sm_ssum[tid]);
        }
        __syncthreads();
    }

    // ---------------- fused aux finalization (last CTA) ----------------
    __threadfence();
    if (tid == 0) sm_ticket = atomicAdd(&g_count, 1u);
    __syncthreads();

    if (sm_ticket == (unsigned)(nblocks - 1)) {
        __threadfence();
        const volatile float* ce = g_ce;
        const volatile float* ss = g_ssum;
        float v = (tid < B_DIM * E_DIM) ? ce[tid] * ss[tid] : 0.0f;
        float* red = (float*)smem;
        red[tid] = v;
        __syncthreads();
        for (int off = 128; off > 0; off >>= 1) {
            if (tid < off) red[tid] += red[tid + off];
            __syncthreads();
        }
        if (tid == 0)
            out_aux[0] = red[0] / (float)S / (float)B_DIM * ALPHA;
        if (tid < B_DIM * E_DIM) { g_ce[tid] = 0.0f; g_ssum[tid] = 0.0f; }
        if (tid == 0) g_count = 0u;
    }
}

extern "C" void kernel_launch(void* const* d_in, const int* in_sizes, int n_in,
                              void* d_out, int out_size) {
    const float* x = (const float*)d_in[0];
    const float* W = (const float*)d_in[1];
    const int T = in_sizes[0] / D_DIM;       // 32768
    const int S = T / B_DIM;                 // 8192
    const int nblocks = T / (TPB * NTILES);  // 256

    float* out     = (float*)d_out;
    float* out_idx = out;                         // [T,8] indices as float
    float* out_w   = out + (size_t)T * TOPK;      // [T,8] weights
    float* out_aux = out + (out_size - 1);        // scalar aux loss

    wsplit_kernel<<<(E_DIM * D_DIM + 1023) / 1024, 1024>>>(W);

    cudaFuncSetAttribute(moe_gate_kernel2,
                         cudaFuncAttributeMaxDynamicSharedMemorySize, SMEM_BYTES);
    moe_gate_kernel2<<<nblocks, THREADS, SMEM_BYTES>>>(x, out_idx, out_w,
                                                       out_aux, S, nblocks);
}